// round 7
// baseline (speedup 1.0000x reference)
#include <cuda_runtime.h>
#include <cstdint>

#define S       512
#define TMAXX   2048
#define OBS     1024
#define CL      8            // cluster size (CTAs)
#define BPC     8            // batches per cluster
#define NSL     64           // S / CL
#define NT      512
#define NCTAS   128          // 16 clusters * 8

// slice payload: c[8][68-padded rows, 64 used] + zp[8] = 552 floats = 2208 bytes
#define BROW    68
#define SLICE_F 552
#define SLICE_B 2208

// ---- dynamic smem layout (float offsets) ----
#define VS_F    0                         // vs2[2][8 slices][SLICE_F]
#define CP_F    (VS_F + 2 * CL * SLICE_F) // cpart[8][8][64] = 4096
#define ZR_F    (CP_F + 4096)             // zred[16]
#define BAR_F   (ZR_F + 16)               // full[2][8] (16 u64) + empty[2] (2 u64) = 36 floats
#define TS_F    (BAR_F + 36)              // Ts[8] ints
#define SMEM_FLOATS (TS_F + 8)
#define SMEM_BYTES  (SMEM_FLOATS * 4)

// ---------------- device tables ----------------
__device__ float g_expA[S * S];      // [n][p]
__device__ float g_expEt[OBS * S];   // [o][n]
__device__ float g_expPi[S];

// ---------------- helpers ----------------
__device__ __forceinline__ float warp_max(float v) {
    #pragma unroll
    for (int o = 16; o; o >>= 1) v = fmaxf(v, __shfl_xor_sync(0xffffffffu, v, o));
    return v;
}
__device__ __forceinline__ float warp_sum(float v) {
    #pragma unroll
    for (int o = 16; o; o >>= 1) v += __shfl_xor_sync(0xffffffffu, v, o);
    return v;
}
__device__ __forceinline__ unsigned long long ffma2(unsigned long long a, unsigned long long b,
                                                    unsigned long long c) {
    unsigned long long d;
    asm("fma.rn.f32x2 %0, %1, %2, %3;" : "=l"(d) : "l"(a), "l"(b), "l"(c));
    return d;
}
__device__ __forceinline__ void lds_2x64(uint32_t addr, unsigned long long& a, unsigned long long& b) {
    asm volatile("ld.shared.v2.u64 {%0, %1}, [%2];" : "=l"(a), "=l"(b) : "r"(addr));
}
__device__ __forceinline__ uint32_t mapa_u32(uint32_t addr, int rank) {
    uint32_t r;
    asm("mapa.shared::cluster.u32 %0, %1, %2;" : "=r"(r) : "r"(addr), "r"(rank));
    return r;
}
__device__ __forceinline__ void mbar_init(uint32_t addr, uint32_t cnt) {
    asm volatile("mbarrier.init.shared.b64 [%0], %1;" :: "r"(addr), "r"(cnt) : "memory");
}
__device__ __forceinline__ void mbar_arrive_expect(uint32_t addr, uint32_t tx) {
    asm volatile("mbarrier.arrive.expect_tx.shared.b64 _, [%0], %1;" :: "r"(addr), "r"(tx) : "memory");
}
__device__ __forceinline__ void mbar_arrive_remote(uint32_t remAddr) {
    asm volatile("mbarrier.arrive.shared::cluster.b64 _, [%0];" :: "r"(remAddr) : "memory");
}
__device__ __forceinline__ void mbar_wait(uint32_t addr, uint32_t parity) {
    uint32_t done;
    asm volatile(
        "{\n\t.reg .pred p;\n\t"
        "mbarrier.try_wait.parity.acquire.cta.shared::cta.b64 p, [%1], %2;\n\t"
        "selp.b32 %0, 1, 0, p;\n\t}"
        : "=r"(done) : "r"(addr), "r"(parity) : "memory");
    if (!done) {
        asm volatile(
            "{\n\t.reg .pred P1;\n\t"
            "WL_%=:\n\t"
            "mbarrier.try_wait.parity.acquire.cta.shared::cta.b64 P1, [%0], %1, 0x989680;\n\t"
            "@P1 bra.uni WD_%=;\n\t"
            "bra.uni WL_%=;\n\t"
            "WD_%=:\n\t}"
            :: "r"(addr), "r"(parity) : "memory");
    }
}
__device__ __forceinline__ void bulk_s2s(uint32_t dst_cluster, uint32_t src_cta,
                                         uint32_t bytes, uint32_t mbar_cluster) {
    asm volatile(
        "cp.async.bulk.shared::cluster.shared::cta.mbarrier::complete_tx::bytes [%0], [%1], %2, [%3];"
        :: "r"(dst_cluster), "r"(src_cta), "r"(bytes), "r"(mbar_cluster) : "memory");
}
__device__ __forceinline__ void fence_proxy_async_() {
    asm volatile("fence.proxy.async.shared::cta;" ::: "memory");
}
__device__ __forceinline__ void cluster_sync_() {
    asm volatile("barrier.cluster.arrive.aligned;\n" ::: "memory");
    asm volatile("barrier.cluster.wait.aligned;\n" ::: "memory");
}

// ---------------- prep kernels (unchanged math) ----------------
__global__ void prep_pi(const float* __restrict__ pi) {
    __shared__ float red[16];
    int tid = threadIdx.x;
    float v = pi[tid];
    float m = warp_max(v);
    if ((tid & 31) == 0) red[tid >> 5] = m;
    __syncthreads();
    float bm = red[0];
    #pragma unroll
    for (int i = 1; i < 16; i++) bm = fmaxf(bm, red[i]);
    __syncthreads();
    float e = expf(v - bm);
    float s = warp_sum(e);
    if ((tid & 31) == 0) red[tid >> 5] = s;
    __syncthreads();
    float bs = 0.f;
    #pragma unroll
    for (int i = 0; i < 16; i++) bs += red[i];
    g_expPi[tid] = e / bs;
}

__global__ void prep_A(const float* __restrict__ trans) {
    __shared__ float red[4];
    int p = blockIdx.x, tid = threadIdx.x;
    int lane = tid & 31, w = tid >> 5;
    float v[4];
    #pragma unroll
    for (int k = 0; k < 4; k++) v[k] = trans[(tid + 128 * k) * S + p];
    float m = fmaxf(fmaxf(v[0], v[1]), fmaxf(v[2], v[3]));
    m = warp_max(m);
    if (lane == 0) red[w] = m;
    __syncthreads();
    float bm = fmaxf(fmaxf(red[0], red[1]), fmaxf(red[2], red[3]));
    __syncthreads();
    float e[4], s = 0.f;
    #pragma unroll
    for (int k = 0; k < 4; k++) { e[k] = expf(v[k] - bm); s += e[k]; }
    s = warp_sum(s);
    if (lane == 0) red[w] = s;
    __syncthreads();
    float bs = red[0] + red[1] + red[2] + red[3];
    float inv = 1.0f / bs;
    #pragma unroll
    for (int k = 0; k < 4; k++) g_expA[(tid + 128 * k) * S + p] = e[k] * inv;
}

__global__ void prep_E(const float* __restrict__ emis) {
    __shared__ float red[8];
    int n = blockIdx.x, tid = threadIdx.x;
    int lane = tid & 31, w = tid >> 5;
    float v[4];
    #pragma unroll
    for (int k = 0; k < 4; k++) v[k] = emis[n * OBS + tid + 256 * k];
    float m = fmaxf(fmaxf(v[0], v[1]), fmaxf(v[2], v[3]));
    m = warp_max(m);
    if (lane == 0) red[w] = m;
    __syncthreads();
    float bm = red[0];
    #pragma unroll
    for (int i = 1; i < 8; i++) bm = fmaxf(bm, red[i]);
    __syncthreads();
    float e[4], s = 0.f;
    #pragma unroll
    for (int k = 0; k < 4; k++) { e[k] = expf(v[k] - bm); s += e[k]; }
    s = warp_sum(s);
    if (lane == 0) red[w] = s;
    __syncthreads();
    float bs = 0.f;
    #pragma unroll
    for (int i = 0; i < 8; i++) bs += red[i];
    float inv = 1.0f / bs;
    #pragma unroll
    for (int k = 0; k < 4; k++) g_expEt[(tid + 256 * k) * S + n] = e[k] * inv;
}

// ---------------- main ----------------
__global__ void __cluster_dims__(CL, 1, 1) __launch_bounds__(NT, 1)
hmm_main(const int* __restrict__ x, const int* __restrict__ T, float* __restrict__ out) {
    extern __shared__ float smf[];
    int* Ts_sh = (int*)(smf + TS_F);

    const int tid  = threadIdx.x;
    const int rank = blockIdx.x & (CL - 1);
    const int cid  = blockIdx.x >> 3;
    const int b0   = cid * BPC;
    const int lane = tid & 31;
    const int nbase = rank * NSL;

    const uint32_t smb = (uint32_t)__cvta_generic_to_shared(smf);
    const uint32_t bar0 = smb + BAR_F * 4u;          // full[s][src] = bar0 + (s*8+src)*8
    const uint32_t ebar0 = bar0 + 16 * 8;            // empty[s] = ebar0 + s*8

    // matmul mapping: group pq handles slice pq (64 p), thread covers 1 n-row, 8 batches
    const int pq  = tid >> 6;
    const int nlm = tid & 63;
    // scale mapping: thread covers (bs, nls)
    const int bs  = tid >> 6;
    const int nls = tid & 63;

    // ---- mbarrier init + initial arms ----
    if (tid == 0) {
        #pragma unroll
        for (int s = 0; s < 2; s++) {
            #pragma unroll
            for (int src = 0; src < CL; src++) mbar_init(bar0 + (s * 8 + src) * 8, 1);
            mbar_init(ebar0 + s * 8, CL);
        }
        #pragma unroll
        for (int s = 0; s < 2; s++)
            #pragma unroll
            for (int src = 0; src < CL; src++)
                if (src != rank) mbar_arrive_expect(bar0 + (s * 8 + src) * 8, SLICE_B);
    }
    if (tid < BPC) Ts_sh[tid] = T[b0 + tid];

    // ---- init v0 into buffer 0 (full local copy, slice layout) ----
    for (int j = tid; j < CL * BPC * NSL; j += NT) {
        int src = j >> 9, b = (j >> 6) & 7, nl = j & 63;
        int p = src * NSL + nl;
        int xb = __ldg(&x[(b0 + b) * TMAXX]);
        smf[VS_F + src * SLICE_F + b * BROW + nl] = g_expEt[xb * S + p] * g_expPi[p];
    }
    __syncthreads();
    if (tid < 64) {
        int src = tid >> 3, b = tid & 7;
        float z = 0.f;
        for (int nl = 0; nl < NSL; nl++) z += smf[VS_F + src * SLICE_F + b * BROW + nl];
        smf[VS_F + src * SLICE_F + 8 * BROW + b] = z;   // zp slot (544 + b)
    }

    // ---- load A slice into registers: thread (pq,nlm) -> A[nbase+nlm][pq*64 .. +64) ----
    unsigned long long Ar[32];
    {
        const float* ab = &g_expA[(nbase + nlm) * S + pq * NSL];
        #pragma unroll
        for (int c = 0; c < 16; c++) {
            float4 a4 = *(const float4*)(ab + 4 * c);
            asm("mov.b64 %0, {%1, %2};" : "=l"(Ar[2 * c])     : "f"(a4.x), "f"(a4.y));
            asm("mov.b64 %0, {%1, %2};" : "=l"(Ar[2 * c + 1]) : "f"(a4.z), "f"(a4.w));
        }
    }
    __syncthreads();
    cluster_sync_();   // barriers + init data visible cluster-wide before any comm

    int maxT = 0;
    #pragma unroll
    for (int b = 0; b < BPC; b++) maxT = max(maxT, Ts_sh[b]);
    const int Tb = Ts_sh[bs];

    float off = 0.f;                 // meaningful in lane 0 of each warp
    int cur = 0;
    uint32_t pf0 = 0, pf1 = 0;       // full-wait parities per buffer (this thread's group barrier)
    uint32_t pe0 = 0, pe1 = 0;       // empty-wait parities (lane 0 of warp 0 only)

    for (int t = 1; ; ++t) {
        const int nxt = cur ^ 1;
        const uint32_t vcur = smb + (VS_F + cur * CL * SLICE_F) * 4u;

        // ---- prefetch E column + observation (hidden under matmul) ----
        int tt = t < TMAXX ? t : TMAXX - 1;
        int xb = __ldg(&x[(b0 + bs) * TMAXX + tt]);
        float Ee = __ldg(&g_expEt[xb * S + nbase + nls]);

        // ---- wait my group's slice (own slice and t==1 need no wait) ----
        if (t > 1 && pq != rank) {
            mbar_wait(bar0 + (cur * 8 + pq) * 8, cur ? pf1 : pf0);
        }

        // ---- matmul: acc[b] += v[b][p] * A (A in regs), p in slice pq ----
        {
            const uint32_t vg = vcur + (pq * SLICE_F) * 4u;
            unsigned long long acc[BPC];
            #pragma unroll
            for (int b = 0; b < BPC; b++) acc[b] = 0ull;
            #pragma unroll
            for (int c = 0; c < 16; c++) {
                #pragma unroll
                for (int b = 0; b < BPC; b++) {
                    unsigned long long v01, v23;
                    lds_2x64(vg + (b * BROW + 4 * c) * 4u, v01, v23);
                    acc[b] = ffma2(v01, Ar[2 * c], acc[b]);
                    acc[b] = ffma2(v23, Ar[2 * c + 1], acc[b]);
                }
            }
            #pragma unroll
            for (int b = 0; b < BPC; b++) {
                float lo, hi;
                asm("mov.b64 {%0, %1}, %2;" : "=f"(lo), "=f"(hi) : "l"(acc[b]));
                smf[CP_F + pq * (BPC * NSL) + b * NSL + nlm] = lo + hi;
            }
        }
        if (t > 1) { if (cur) pf1 ^= 1; else pf0 ^= 1; }
        __syncthreads();   // sync#1: all slices consumed, cpart complete, zp[cur] visible

        // ---- per-warp Z of v_t: lane 0 computes log/rcp, broadcasts rz ----
        float rz;
        if (lane == 0) {
            float z = 0.f;
            #pragma unroll
            for (int src = 0; src < CL; src++)
                z += smf[VS_F + cur * CL * SLICE_F + src * SLICE_F + 8 * BROW + bs];
            float tot = off + logf(z);
            if (rank == 0 && Tb == t) out[b0 + bs] = tot;   // duplicate store by 2 warps: benign
            off = tot;
            rz = 1.0f / z;
        }
        if (t == maxT) break;
        rz = __shfl_sync(0xffffffffu, rz, 0);

        // ---- reduce partials, scale, store own slice of v_{t+1} ----
        {
            float ssum = 0.f;
            #pragma unroll
            for (int q = 0; q < 8; q++) ssum += smf[CP_F + q * (BPC * NSL) + bs * NSL + nls];
            float c = ssum * Ee * rz;
            smf[VS_F + nxt * CL * SLICE_F + rank * SLICE_F + bs * BROW + nls] = c;
            float zs = warp_sum(c);
            if (lane == 0) smf[ZR_F + (tid >> 5)] = zs;
        }
        __syncthreads();   // sync#2: slice + zred complete

        // ---- housekeeping + comm (warp 0 only) ----
        if (tid < 32) {
            if (lane < 8) {
                // zp for own slice of v_{t+1}
                smf[VS_F + nxt * CL * SLICE_F + rank * SLICE_F + 8 * BROW + lane] =
                    smf[ZR_F + 2 * lane] + smf[ZR_F + 2 * lane + 1];
            } else if (lane < 16) {
                // re-arm full[cur][src] for its next fill (skip at t==1: init armed it)
                int src = lane - 8;
                if (t > 1 && src != rank) mbar_arrive_expect(bar0 + (cur * 8 + src) * 8, SLICE_B);
            }
            __syncwarp();
            if (lane >= 16 && lane < 24) {
                // tell all CTAs buffer cur is free (ordered after re-arm)
                mbar_arrive_remote(mapa_u32(ebar0 + cur * 8, lane - 16));
            }
            if (lane == 0) {
                // gate copies on peers done reading buffer nxt (skip at t==1: never read)
                if (t > 1) {
                    mbar_wait(ebar0 + nxt * 8, nxt ? pe1 : pe0);
                    if (nxt) pe1 ^= 1; else pe0 ^= 1;
                }
                fence_proxy_async_();
                uint32_t srcaddr = smb + (VS_F + nxt * CL * SLICE_F + rank * SLICE_F) * 4u;
                #pragma unroll
                for (int r = 0; r < CL; r++) {
                    if (r == rank) continue;
                    uint32_t dst = mapa_u32(srcaddr, r);
                    uint32_t mb  = mapa_u32(bar0 + (nxt * 8 + rank) * 8, r);
                    bulk_s2s(dst, srcaddr, SLICE_B, mb);
                }
            }
        }
        cur = nxt;
    }
}

// ---------------- launch ----------------
extern "C" void kernel_launch(void* const* d_in, const int* in_sizes, int n_in,
                              void* d_out, int out_size) {
    const int*   x     = (const int*)d_in[0];
    const int*   T     = (const int*)d_in[1];
    const float* pi    = (const float*)d_in[2];
    const float* trans = (const float*)d_in[3];
    const float* emis  = (const float*)d_in[4];
    float* out = (float*)d_out;

    cudaFuncSetAttribute(hmm_main, cudaFuncAttributeMaxDynamicSharedMemorySize, SMEM_BYTES);

    prep_pi<<<1, S>>>(pi);
    prep_A<<<S, 128>>>(trans);
    prep_E<<<S, 256>>>(emis);
    hmm_main<<<NCTAS, NT, SMEM_BYTES>>>(x, T, out);
}

// round 9
// speedup vs baseline: 3.4259x; 3.4259x over previous
#include <cuda_runtime.h>
#include <cuda_bf16.h>
#include <cstdint>

#define S       512
#define TMAXX   2048
#define OBS     1024
#define CL      4
#define BPC     4
#define NT      512
#define NCTAS   128

// B slice: 8 rows x 136 bf16 (128 used + pad; zp f32 at byte 256 of row b)
#define BROWB   272
#define SLICEB  2176            // 8 * 272
#define BUF_B   8704            // 4 slices

// smem layout (bytes)
#define B_OFF   0               // [2][4][SLICEB] = 17408
#define CP_OFF  17408           // cp[2 kh][128 n][8 b] f32 = 8192
#define CP_KH   4096
#define ZR_OFF  25600           // zr[16 w][2 q] float2 = 256
#define RZ_OFF  25856           // rz[4]
#define TS_OFF  25872           // Ts[4]
#define BAR_OFF 25888           // full[2][4]=64B, empty[2]=16B
#define SMEM_BYTES (BAR_OFF + 96)

// ---------------- device tables ----------------
__device__ float g_expA[S * S];      // [n][p]
__device__ float g_expEt[OBS * S];   // [o][n]
__device__ float g_expPi[S];

// ---------------- helpers ----------------
__device__ __forceinline__ float warp_max(float v) {
    #pragma unroll
    for (int o = 16; o; o >>= 1) v = fmaxf(v, __shfl_xor_sync(0xffffffffu, v, o));
    return v;
}
__device__ __forceinline__ float warp_sum(float v) {
    #pragma unroll
    for (int o = 16; o; o >>= 1) v += __shfl_xor_sync(0xffffffffu, v, o);
    return v;
}
__device__ __forceinline__ uint32_t mapa_u32(uint32_t addr, int rank) {
    uint32_t r;
    asm("mapa.shared::cluster.u32 %0, %1, %2;" : "=r"(r) : "r"(addr), "r"(rank));
    return r;
}
__device__ __forceinline__ void mbar_init(uint32_t addr, uint32_t cnt) {
    asm volatile("mbarrier.init.shared.b64 [%0], %1;" :: "r"(addr), "r"(cnt) : "memory");
}
__device__ __forceinline__ void mbar_arrive_expect(uint32_t addr, uint32_t tx) {
    asm volatile("mbarrier.arrive.expect_tx.shared.b64 _, [%0], %1;" :: "r"(addr), "r"(tx) : "memory");
}
__device__ __forceinline__ void mbar_arrive_remote(uint32_t remAddr) {
    asm volatile("mbarrier.arrive.shared::cluster.b64 _, [%0];" :: "r"(remAddr) : "memory");
}
__device__ __forceinline__ void mbar_wait(uint32_t addr, uint32_t parity) {
    uint32_t done;
    asm volatile(
        "{\n\t.reg .pred p;\n\t"
        "mbarrier.try_wait.parity.acquire.cta.shared::cta.b64 p, [%1], %2;\n\t"
        "selp.b32 %0, 1, 0, p;\n\t}"
        : "=r"(done) : "r"(addr), "r"(parity) : "memory");
    if (!done) {
        asm volatile(
            "{\n\t.reg .pred P1;\n\t"
            "WL_%=:\n\t"
            "mbarrier.try_wait.parity.acquire.cta.shared::cta.b64 P1, [%0], %1, 0x989680;\n\t"
            "@P1 bra.uni WD_%=;\n\t"
            "bra.uni WL_%=;\n\t"
            "WD_%=:\n\t}"
            :: "r"(addr), "r"(parity) : "memory");
    }
}
__device__ __forceinline__ void bulk_s2s(uint32_t dst_cluster, uint32_t src_cta,
                                         uint32_t bytes, uint32_t mbar_cluster) {
    asm volatile(
        "cp.async.bulk.shared::cluster.shared::cta.mbarrier::complete_tx::bytes [%0], [%1], %2, [%3];"
        :: "r"(dst_cluster), "r"(src_cta), "r"(bytes), "r"(mbar_cluster) : "memory");
}
__device__ __forceinline__ void fence_proxy_async_() {
    asm volatile("fence.proxy.async.shared::cta;" ::: "memory");
}
__device__ __forceinline__ void cluster_sync_() {
    asm volatile("barrier.cluster.arrive.aligned;\n" ::: "memory");
    asm volatile("barrier.cluster.wait.aligned;\n" ::: "memory");
}
__device__ __forceinline__ uint32_t pk_bf2(float lo, float hi) {
    __nv_bfloat162 h = __floats2bfloat162_rn(lo, hi);   // x=lo (low half), y=hi
    return *(uint32_t*)&h;
}
__device__ __forceinline__ uint32_t lds_u32(uint32_t addr) {
    uint32_t v;
    asm volatile("ld.shared.u32 %0, [%1];" : "=r"(v) : "r"(addr));
    return v;
}
__device__ __forceinline__ void mma16816(float& c0, float& c1, float& c2, float& c3,
                                         uint32_t a0, uint32_t a1, uint32_t a2, uint32_t a3,
                                         uint32_t b0, uint32_t b1) {
    asm volatile(
        "mma.sync.aligned.m16n8k16.row.col.f32.bf16.bf16.f32 "
        "{%0,%1,%2,%3}, {%4,%5,%6,%7}, {%8,%9}, {%0,%1,%2,%3};"
        : "+f"(c0), "+f"(c1), "+f"(c2), "+f"(c3)
        : "r"(a0), "r"(a1), "r"(a2), "r"(a3), "r"(b0), "r"(b1));
}

// ---------------- prep kernels (unchanged math) ----------------
__global__ void prep_pi(const float* __restrict__ pi) {
    __shared__ float red[16];
    int tid = threadIdx.x;
    float v = pi[tid];
    float m = warp_max(v);
    if ((tid & 31) == 0) red[tid >> 5] = m;
    __syncthreads();
    float bm = red[0];
    #pragma unroll
    for (int i = 1; i < 16; i++) bm = fmaxf(bm, red[i]);
    __syncthreads();
    float e = expf(v - bm);
    float s = warp_sum(e);
    if ((tid & 31) == 0) red[tid >> 5] = s;
    __syncthreads();
    float bs = 0.f;
    #pragma unroll
    for (int i = 0; i < 16; i++) bs += red[i];
    g_expPi[tid] = e / bs;
}

__global__ void prep_A(const float* __restrict__ trans) {
    __shared__ float red[4];
    int p = blockIdx.x, tid = threadIdx.x;
    int lane = tid & 31, w = tid >> 5;
    float v[4];
    #pragma unroll
    for (int k = 0; k < 4; k++) v[k] = trans[(tid + 128 * k) * S + p];
    float m = fmaxf(fmaxf(v[0], v[1]), fmaxf(v[2], v[3]));
    m = warp_max(m);
    if (lane == 0) red[w] = m;
    __syncthreads();
    float bm = fmaxf(fmaxf(red[0], red[1]), fmaxf(red[2], red[3]));
    __syncthreads();
    float e[4], s = 0.f;
    #pragma unroll
    for (int k = 0; k < 4; k++) { e[k] = expf(v[k] - bm); s += e[k]; }
    s = warp_sum(s);
    if (lane == 0) red[w] = s;
    __syncthreads();
    float bs = red[0] + red[1] + red[2] + red[3];
    float inv = 1.0f / bs;
    #pragma unroll
    for (int k = 0; k < 4; k++) g_expA[(tid + 128 * k) * S + p] = e[k] * inv;
}

__global__ void prep_E(const float* __restrict__ emis) {
    __shared__ float red[8];
    int n = blockIdx.x, tid = threadIdx.x;
    int lane = tid & 31, w = tid >> 5;
    float v[4];
    #pragma unroll
    for (int k = 0; k < 4; k++) v[k] = emis[n * OBS + tid + 256 * k];
    float m = fmaxf(fmaxf(v[0], v[1]), fmaxf(v[2], v[3]));
    m = warp_max(m);
    if (lane == 0) red[w] = m;
    __syncthreads();
    float bm = red[0];
    #pragma unroll
    for (int i = 1; i < 8; i++) bm = fmaxf(bm, red[i]);
    __syncthreads();
    float e[4], s = 0.f;
    #pragma unroll
    for (int k = 0; k < 4; k++) { e[k] = expf(v[k] - bm); s += e[k]; }
    s = warp_sum(s);
    if (lane == 0) red[w] = s;
    __syncthreads();
    float bs = 0.f;
    #pragma unroll
    for (int i = 0; i < 8; i++) bs += red[i];
    float inv = 1.0f / bs;
    #pragma unroll
    for (int k = 0; k < 4; k++) g_expEt[(tid + 256 * k) * S + n] = e[k] * inv;
}

// ---------------- main: HMMA scaled forward ----------------
__global__ void __cluster_dims__(CL, 1, 1) __launch_bounds__(NT, 1)
hmm_main(const int* __restrict__ x, const int* __restrict__ T, float* __restrict__ out) {
    extern __shared__ char smc[];
    float* smf = (float*)smc;
    int* Ts_sh = (int*)(smc + TS_OFF);

    const int tid  = threadIdx.x;
    const int wid  = tid >> 5, lane = tid & 31;
    const int rank = blockIdx.x & (CL - 1);
    const int b0   = (blockIdx.x >> 2) * BPC;
    const int nbase = rank * 128;

    const uint32_t smb  = (uint32_t)__cvta_generic_to_shared(smc);
    const uint32_t barF = smb + BAR_OFF;          // full[s][src] = barF + (s*4+src)*8
    const uint32_t barE = smb + BAR_OFF + 64;     // empty[s]

    // fragment coords
    const int g  = lane >> 2, tg = lane & 3;
    const int kh = wid & 1;                       // k half: chunks kh*16 .. +15
    const int mrow = (wid >> 1) * 16;             // rows mrow..mrow+15

    // epilogue coords
    const int ne = tid >> 2, q = tid & 3;         // n row, batch pair q -> b=2q,2q+1

    // ---- barriers ----
    if (tid == 0) {
        #pragma unroll
        for (int s = 0; s < 2; s++) {
            #pragma unroll
            for (int src = 0; src < CL; src++) mbar_init(barF + (s * 4 + src) * 8, 1);
            mbar_init(barE + s * 8, CL);
        }
        #pragma unroll
        for (int s = 0; s < 2; s++)
            #pragma unroll
            for (int src = 0; src < CL; src++)
                if (src != rank) mbar_arrive_expect(barF + (s * 4 + src) * 8, SLICEB);
    }
    if (tid < BPC) Ts_sh[tid] = T[b0 + tid];

    // ---- zero both B buffers ----
    for (int j = tid; j < 2 * BUF_B / 4; j += NT) ((uint32_t*)smc)[B_OFF / 4 + j] = 0u;
    __syncthreads();

    // ---- v0: all 4 slices locally, rows b<4 ----
    int xb0[BPC];
    #pragma unroll
    for (int b = 0; b < BPC; b++) xb0[b] = __ldg(&x[(b0 + b) * TMAXX]);
    for (int j = tid; j < 4 * BPC * 128; j += NT) {
        int s = j >> 9, b = (j >> 7) & 3, pl = j & 127;
        int p = s * 128 + pl;
        float v = __ldg(&g_expEt[xb0[b] * S + p]) * __ldg(&g_expPi[p]);
        *(uint16_t*)(smc + B_OFF + s * SLICEB + b * BROWB + pl * 2) =
            __bfloat16_as_ushort(__float2bfloat16(v));
    }
    // zp for buffer 0 (exact f32)
    if (tid < 16) {
        int s = tid >> 2, b = tid & 3;
        float z = 0.f;
        for (int pl = 0; pl < 128; pl++) {
            int p = s * 128 + pl;
            z += __ldg(&g_expEt[xb0[b] * S + p]) * __ldg(&g_expPi[p]);
        }
        *(float*)(smc + B_OFF + s * SLICEB + b * BROWB + 256) = z;
    }

    // ---- A fragments resident in registers (64 regs) ----
    uint32_t Ar[16][4];
    {
        const float* r0p = &g_expA[(nbase + mrow + g) * S + kh * 256 + tg * 2];
        const float* r1p = r0p + 8 * S;
        #pragma unroll
        for (int c = 0; c < 16; c++) {
            const float* a0 = r0p + c * 16;
            const float* a1 = r1p + c * 16;
            Ar[c][0] = pk_bf2(__ldg(a0),     __ldg(a0 + 1));
            Ar[c][1] = pk_bf2(__ldg(a1),     __ldg(a1 + 1));
            Ar[c][2] = pk_bf2(__ldg(a0 + 8), __ldg(a0 + 9));
            Ar[c][3] = pk_bf2(__ldg(a1 + 8), __ldg(a1 + 9));
        }
    }
    __syncthreads();
    cluster_sync_();   // barriers + v0 visible before any comm

    int maxT = 0;
    #pragma unroll
    for (int b = 0; b < BPC; b++) maxT = max(maxT, Ts_sh[b]);

    float off = 0.f;                 // warp 0 lanes 0..3
    int cur = 0;
    uint32_t pf0 = 0, pf1 = 0, pe0 = 0, pe1 = 0;

    for (int t = 1; ; ++t) {
        const int nxt = cur ^ 1;

        // ---- prefetch E (epilogue threads, q<2) ----
        float Ee0 = 0.f, Ee1 = 0.f;
        if (q < 2) {
            int tt = t < TMAXX ? t : TMAXX - 1;
            int xA = __ldg(&x[(b0 + 2 * q) * TMAXX + tt]);
            int xB = __ldg(&x[(b0 + 2 * q + 1) * TMAXX + tt]);
            Ee0 = __ldg(&g_expEt[xA * S + nbase + ne]);
            Ee1 = __ldg(&g_expEt[xB * S + nbase + ne]);
        }

        // ---- wait needed slices ----
        if (t > 1) {
            uint32_t par = cur ? pf1 : pf0;
            if (wid == 0) {
                #pragma unroll
                for (int src = 0; src < CL; src++)
                    if (src != rank) mbar_wait(barF + (cur * 4 + src) * 8, par);
            } else {
                int s0 = kh * 2, s1 = kh * 2 + 1;
                if (s0 != rank) mbar_wait(barF + (cur * 4 + s0) * 8, par);
                if (s1 != rank) mbar_wait(barF + (cur * 4 + s1) * 8, par);
            }
            if (cur) pf1 ^= 1; else pf0 ^= 1;
        }

        // ---- warp 0: z / out / rz ----
        if (wid == 0 && lane < BPC) {
            int b = lane;
            float z = 0.f;
            #pragma unroll
            for (int s = 0; s < CL; s++)
                z += *(float*)(smc + B_OFF + cur * BUF_B + s * SLICEB + b * BROWB + 256);
            float tot = off + logf(z);
            if (rank == 0 && Ts_sh[b] == t) out[b0 + b] = tot;
            off = tot;
            smf[RZ_OFF / 4 + b] = 1.0f / z;
        }
        if (t == maxT) break;

        // ---- MMA: partial D over this warp's k half ----
        {
            const uint32_t vwb = smb + B_OFF + cur * BUF_B + kh * (2 * SLICEB)
                               + g * BROWB + tg * 4;
            float c0 = 0.f, c1 = 0.f, c2 = 0.f, c3 = 0.f;
            #pragma unroll
            for (int c = 0; c < 16; c++) {
                uint32_t boff = (uint32_t)((c >> 3) * SLICEB + (c & 7) * 32);
                uint32_t bb0 = lds_u32(vwb + boff);
                uint32_t bb1 = lds_u32(vwb + boff + 16);
                mma16816(c0, c1, c2, c3, Ar[c][0], Ar[c][1], Ar[c][2], Ar[c][3], bb0, bb1);
            }
            // cp[kh][n][b] : rows mrow+g and mrow+g+8, cols 2tg, 2tg+1
            *(float2*)(smc + CP_OFF + kh * CP_KH + (mrow + g) * 32 + tg * 8)     = make_float2(c0, c1);
            *(float2*)(smc + CP_OFF + kh * CP_KH + (mrow + g + 8) * 32 + tg * 8) = make_float2(c2, c3);
        }
        __syncthreads();   // sync#1: B[cur] consumed, cp complete, rz visible

        // ---- epilogue: combine k halves, scale, store own slice; z partials ----
        float zb0 = 0.f, zb1 = 0.f;
        if (q < 2) {
            float2 p0 = *(float2*)(smc + CP_OFF + ne * 32 + q * 8);
            float2 p1 = *(float2*)(smc + CP_OFF + CP_KH + ne * 32 + q * 8);
            float rz0 = smf[RZ_OFF / 4 + 2 * q];
            float rz1 = smf[RZ_OFF / 4 + 2 * q + 1];
            zb0 = (p0.x + p1.x) * Ee0 * rz0;
            zb1 = (p0.y + p1.y) * Ee1 * rz1;
            uint32_t base = (uint32_t)(B_OFF + nxt * BUF_B + rank * SLICEB + ne * 2);
            *(uint16_t*)(smc + base + (2 * q) * BROWB)     = __bfloat16_as_ushort(__float2bfloat16(zb0));
            *(uint16_t*)(smc + base + (2 * q + 1) * BROWB) = __bfloat16_as_ushort(__float2bfloat16(zb1));
        }
        // warp z reduction over n (lanes with same q)
        #pragma unroll
        for (int o = 16; o >= 4; o >>= 1) {
            zb0 += __shfl_xor_sync(0xffffffffu, zb0, o);
            zb1 += __shfl_xor_sync(0xffffffffu, zb1, o);
        }
        if (lane < 2) *(float2*)(smc + ZR_OFF + wid * 16 + lane * 8) = make_float2(zb0, zb1);
        __syncthreads();   // sync#2: slice + zr complete

        // ---- comm (warp 0) ----
        if (wid == 0) {
            if (lane < BPC) {
                int b = lane;
                float zs = 0.f;
                #pragma unroll
                for (int w = 0; w < 16; w++)
                    zs += *(float*)(smc + ZR_OFF + w * 16 + (b >> 1) * 8 + (b & 1) * 4);
                *(float*)(smc + B_OFF + nxt * BUF_B + rank * SLICEB + b * BROWB + 256) = zs;
            } else if (lane >= 4 && lane < 8) {
                int src = lane - 4;
                if (t > 1 && src != rank) mbar_arrive_expect(barF + (cur * 4 + src) * 8, SLICEB);
            }
            __syncwarp();
            if (lane >= 8 && lane < 8 + CL) {
                mbar_arrive_remote(mapa_u32(barE + cur * 8, lane - 8));
            }
            if (lane == 0) {
                if (t > 1) {
                    mbar_wait(barE + nxt * 8, nxt ? pe1 : pe0);
                    if (nxt) pe1 ^= 1; else pe0 ^= 1;
                }
                fence_proxy_async_();
                uint32_t srcaddr = smb + B_OFF + nxt * BUF_B + rank * SLICEB;
                #pragma unroll
                for (int r = 0; r < CL; r++) {
                    if (r == rank) continue;
                    bulk_s2s(mapa_u32(srcaddr, r), srcaddr, SLICEB,
                             mapa_u32(barF + (nxt * 4 + rank) * 8, r));
                }
            }
        }
        cur = nxt;
    }

    cluster_sync_();   // keep smem alive until all in-flight copies drain
}

// ---------------- launch ----------------
extern "C" void kernel_launch(void* const* d_in, const int* in_sizes, int n_in,
                              void* d_out, int out_size) {
    const int*   x     = (const int*)d_in[0];
    const int*   T     = (const int*)d_in[1];
    const float* pi    = (const float*)d_in[2];
    const float* trans = (const float*)d_in[3];
    const float* emis  = (const float*)d_in[4];
    float* out = (float*)d_out;

    cudaFuncSetAttribute(hmm_main, cudaFuncAttributeMaxDynamicSharedMemorySize, SMEM_BYTES);

    prep_pi<<<1, S>>>(pi);
    prep_A<<<S, 128>>>(trans);
    prep_E<<<S, 256>>>(emis);
    hmm_main<<<NCTAS, NT, SMEM_BYTES>>>(x, T, out);
}